// round 12
// baseline (speedup 1.0000x reference)
#include <cuda_runtime.h>
#include <cstdint>

#define B_ 32
#define I_ 16384
#define H_ 1024
#define T_ 10
#define NSEG 16
#define SLOT 256   // max actives per 1024-i segment per (t,b); Binom(1024,0.1) never near 256

// ---------------- scratch (static device memory; no runtime alloc) ----------------
__device__ unsigned g_masks[T_ * I_];                    // bit b = spike(b,i,t)
__device__ int      g_list2[B_ * T_ * NSEG * SLOT];      // slotted active-i lists
__device__ int      g_segLen[B_ * T_ * NSEG];
__device__ float    g_weff[(size_t)I_ * H_];             // weight * synaptic_strength
__device__ float    g_partial[(size_t)NSEG * 4 * T_ * H_ * 8]; // [seg*4+bg][t][h][bi]
__device__ float    g_acc[32];                           // diag: v[0..9], rate[10..19], thr[20..29]
__device__ int      g_cnt;                               // last-block ticket for k_scan

// ---------------- kernel 0: fused spike-pack + w_eff materialization ----------------
// blocks [0,16): pack (1024 i's each); blocks [16,4112): weff (4096 elems each)
__global__ void __launch_bounds__(1024) k0(const float* __restrict__ spikes,
                                           const float* __restrict__ w,
                                           const float* __restrict__ s) {
    if (blockIdx.x < 16) {
        int i = blockIdx.x * 1024 + threadIdx.x;
        unsigned m[T_];
#pragma unroll
        for (int t = 0; t < T_; t++) m[t] = 0;
        const char* base = (const char*)spikes + (size_t)i * (T_ * 4);
#pragma unroll 4
        for (int b = 0; b < B_; b++) {
            const float2* p = (const float2*)(base + (size_t)b * ((size_t)I_ * T_ * 4));
            float2 v0 = p[0], v1 = p[1], v2 = p[2], v3 = p[3], v4 = p[4];
            unsigned bit = 1u << b;
            if (v0.x != 0.0f) m[0] |= bit;
            if (v0.y != 0.0f) m[1] |= bit;
            if (v1.x != 0.0f) m[2] |= bit;
            if (v1.y != 0.0f) m[3] |= bit;
            if (v2.x != 0.0f) m[4] |= bit;
            if (v2.y != 0.0f) m[5] |= bit;
            if (v3.x != 0.0f) m[6] |= bit;
            if (v3.y != 0.0f) m[7] |= bit;
            if (v4.x != 0.0f) m[8] |= bit;
            if (v4.y != 0.0f) m[9] |= bit;
        }
#pragma unroll
        for (int t = 0; t < T_; t++) g_masks[t * I_ + i] = m[t];
        if (blockIdx.x == 0 && threadIdx.x < 32) g_acc[threadIdx.x] = 0.0f;
        if (blockIdx.x == 0 && threadIdx.x == 0) g_cnt = 0;
    } else {
        size_t idx = ((size_t)(blockIdx.x - 16) * 1024 + threadIdx.x) * 4;
        float4 a = *(const float4*)(w + idx);
        float4 c = *(const float4*)(s + idx);
        float4 r;
        r.x = a.x * c.x; r.y = a.y * c.y; r.z = a.z * c.z; r.w = a.w * c.w;
        *(float4*)(&g_weff[idx]) = r;
    }
}

// ---------------- kernel 1: slotted compaction (deterministic, coalesced) ----------
__global__ void __launch_bounds__(256) k_lists() {
    int tb = blockIdx.x;         // t*32 + b
    int t  = tb >> 5;
    int b  = tb & 31;
    int tid = threadIdx.x;
    int seg = tid >> 4;
    int sub = tid & 15;
    const uint4* mrow4 = (const uint4*)(g_masks + t * I_ + seg * 1024);
    // pass 1: count
    int c = 0;
#pragma unroll
    for (int j = 0; j < 16; j++) {
        uint4 m4 = mrow4[sub + j * 16];
        c += ((m4.x >> b) & 1u) + ((m4.y >> b) & 1u) + ((m4.z >> b) & 1u) + ((m4.w >> b) & 1u);
    }
    // inclusive scan within 16-thread group
    int inc = c;
#pragma unroll
    for (int d = 1; d < 16; d <<= 1) {
        int n = __shfl_up_sync(0xffffffffu, inc, d, 16);
        if (sub >= d) inc += n;
    }
    int total = __shfl_sync(0xffffffffu, inc, 15, 16);
    int off = inc - c;
    if (sub == 0) g_segLen[tb * NSEG + seg] = total < SLOT ? total : SLOT;
    int* slot = g_list2 + ((size_t)tb * NSEG + seg) * SLOT;
    // pass 2: write (L1 hits)
#pragma unroll
    for (int j = 0; j < 16; j++) {
        uint4 m4 = mrow4[sub + j * 16];
        int i0 = seg * 1024 + sub * 4 + j * 64;
        if ((m4.x >> b) & 1u) { if (off < SLOT) slot[off] = i0 + 0; off++; }
        if ((m4.y >> b) & 1u) { if (off < SLOT) slot[off] = i0 + 1; off++; }
        if ((m4.z >> b) & 1u) { if (off < SLOT) slot[off] = i0 + 2; off++; }
        if ((m4.w >> b) & 1u) { if (off < SLOT) slot[off] = i0 + 3; off++; }
    }
}

// ---------------- kernel 2: sparse row-accumulate "GEMM" ----------------
// grid (NSEG, 8, T_*4): (i-seg, h-tile-128, t & batch-group); block 256: warp = b within group
__global__ void __launch_bounds__(256) k_sgemm() {
    int seg  = blockIdx.x;
    int hblk = blockIdx.y;
    int t    = blockIdx.z >> 2;
    int bg   = blockIdx.z & 3;
    int warp = threadIdx.x >> 5;
    int lane = threadIdx.x & 31;
    int b    = bg * 8 + warp;
    int tb   = t * 32 + b;
    int len  = g_segLen[tb * NSEG + seg];
    const int4* lst4 = (const int4*)(g_list2 + ((size_t)tb * NSEG + seg) * SLOT);
    const float* W = g_weff + hblk * 128 + lane * 4;
    float ax = 0.f, ay = 0.f, az = 0.f, aw = 0.f;
    int k4 = len >> 2;
    for (int q = 0; q < k4; q++) {
        int4 id = lst4[q];
        float4 w0 = *(const float4*)(W + (size_t)id.x * H_);
        float4 w1 = *(const float4*)(W + (size_t)id.y * H_);
        float4 w2 = *(const float4*)(W + (size_t)id.z * H_);
        float4 w3 = *(const float4*)(W + (size_t)id.w * H_);
        ax += w0.x; ay += w0.y; az += w0.z; aw += w0.w;
        ax += w1.x; ay += w1.y; az += w1.z; aw += w1.w;
        ax += w2.x; ay += w2.y; az += w2.z; aw += w2.w;
        ax += w3.x; ay += w3.y; az += w3.z; aw += w3.w;
    }
    for (int k = k4 * 4; k < len; k++) {
        int i = ((const int*)lst4)[k];
        float4 w0 = *(const float4*)(W + (size_t)i * H_);
        ax += w0.x; ay += w0.y; az += w0.z; aw += w0.w;
    }
    // transpose to [h][bi] via smem for coalesced reads downstream
    __shared__ float sh[8][132];
    sh[warp][lane * 4 + 0] = ax;
    sh[warp][lane * 4 + 1] = ay;
    sh[warp][lane * 4 + 2] = az;
    sh[warp][lane * 4 + 3] = aw;
    __syncthreads();
    int h  = threadIdx.x >> 1;        // local h 0..127
    int hq = (threadIdx.x & 1) * 4;   // bi quad 0 or 4
    float4 o;
    o.x = sh[hq + 0][h]; o.y = sh[hq + 1][h]; o.z = sh[hq + 2][h]; o.w = sh[hq + 3][h];
    size_t sb = (size_t)seg * 4 + bg;
    float* dst = g_partial + ((sb * T_ + t) * H_ + (size_t)hblk * 128) * 8;
    *(float4*)(dst + h * 8 + hq) = o;
}

// ---------------- kernel 3: two-phase scan, 2 h per block (4x block parallelism) ---
// Phase 1: all 256 threads cooperatively reduce 640 (t,hl,b) slab-sums into smem
// Phase 2: warps 0-1 run the sequential scan for their h; fused diag final via ticket
__global__ void __launch_bounds__(256) k_scan(const float* __restrict__ thr_in,
                                              const float* __restrict__ fre_in,
                                              const float* __restrict__ tau_mem,
                                              const float* __restrict__ tau_syn,
                                              const float* __restrict__ target,
                                              const float* __restrict__ lr,
                                              float* __restrict__ out) {
    __shared__ float sw[T_][2][32];   // [t][h_local][b]
    __shared__ float sacc[32];
    __shared__ int slast;
    if (threadIdx.x < 32) sacc[threadIdx.x] = 0.0f;

    int hbase = blockIdx.x * 2;

    // ---- phase 1: 640 outputs spread over 256 threads; seg order 0..15 (unchanged)
    for (int o = threadIdx.x; o < T_ * 2 * 32; o += 256) {
        int b  = o & 31;
        int hl = (o >> 5) & 1;
        int t  = o >> 6;
        int bg = b >> 3;
        int bi = b & 7;
        const float* P = g_partial + (((size_t)bg * T_ + t) * H_ + (hbase + hl)) * 8 + bi;
        float a = 0.0f;
#pragma unroll
        for (int seg = 0; seg < NSEG; seg++)
            a += P[(size_t)seg * 4 * T_ * H_ * 8];
        sw[t][hl][b] = a;
    }
    __syncthreads();

    // ---- phase 2: warps 0-1 each scan one h
    int warp = threadIdx.x >> 5;
    int lane = threadIdx.x & 31;   // = b
    if (warp < 2) {
        int hg = hbase + warp;
        float am  = expf(-0.001f / tau_mem[0]);
        float as  = expf(-0.001f / tau_syn[0]);
        float tgt = target[0];
        float hlr = lr[0];
        float thr = thr_in[hg];
        float fre = fre_in[hg];
        float v = 0.0f, isyn = 0.0f;
        float sp[T_];
#pragma unroll
        for (int t = 0; t < T_; t++) {
            float w = sw[t][warp][lane];
            isyn = as * isyn + w;
            v    = am * v + isyn;
            unsigned m = __ballot_sync(0xffffffffu, v >= thr);
            bool fired = (m >> lane) & 1u;
            if (fired) v -= thr;
            sp[t] = fired ? 1.0f : 0.0f;
            float rate = (float)__popc(m) * (1.0f / 32.0f);
            fre = 0.99f * fre + 0.01f * rate;
            thr += hlr * (fre - tgt);
            float vs = v;
#pragma unroll
            for (int o = 16; o > 0; o >>= 1) vs += __shfl_down_sync(0xffffffffu, vs, o);
            if (lane == 0) {
                atomicAdd(&sacc[t], vs);
                atomicAdd(&sacc[10 + t], rate);
                atomicAdd(&sacc[20 + t], thr);
            }
        }
        // spikes: out[b][h][t] — 40 contiguous bytes per thread, 5x float2
        float2* o2 = (float2*)(out + (size_t)lane * H_ * T_ + (size_t)hg * T_);
#pragma unroll
        for (int j = 0; j < 5; j++) {
            float2 p; p.x = sp[2 * j]; p.y = sp[2 * j + 1];
            o2[j] = p;
        }
    }
    __syncthreads();
    if (threadIdx.x == 0) {
#pragma unroll
        for (int i = 0; i < 30; i++) atomicAdd(&g_acc[i], sacc[i]);
        __threadfence();
        int p = atomicAdd(&g_cnt, 1);
        slast = (p == (int)gridDim.x - 1);
    }
    __syncthreads();
    if (slast && threadIdx.x < 30) {
        float vfin = atomicAdd(&g_acc[threadIdx.x], 0.0f);  // coherent L2 read
        float scale = (threadIdx.x < 10) ? (1.0f / (B_ * H_)) : (1.0f / H_);
        out[(size_t)B_ * H_ * T_ + threadIdx.x] = vfin * scale;
    }
}

extern "C" void kernel_launch(void* const* d_in, const int* in_sizes, int n_in,
                              void* d_out, int out_size) {
    const float* spikes  = (const float*)d_in[0];
    const float* weight  = (const float*)d_in[1];
    const float* syn     = (const float*)d_in[2];
    const float* thr     = (const float*)d_in[3];
    const float* fre     = (const float*)d_in[4];
    const float* tau_mem = (const float*)d_in[5];
    const float* tau_syn = (const float*)d_in[6];
    const float* target  = (const float*)d_in[7];
    const float* lr      = (const float*)d_in[8];
    float* out = (float*)d_out;

    k0<<<16 + (int)((size_t)I_ * H_ / 4 / 1024), 1024>>>(spikes, weight, syn);
    k_lists<<<B_ * T_, 256>>>();
    k_sgemm<<<dim3(NSEG, 8, T_ * 4), 256>>>();
    k_scan<<<H_ / 2, 256>>>(thr, fre, tau_mem, tau_syn, target, lr, out);
}

// round 13
// speedup vs baseline: 1.0466x; 1.0466x over previous
#include <cuda_runtime.h>
#include <cstdint>

#define B_ 32
#define I_ 16384
#define H_ 1024
#define T_ 10
#define NSEG 16
#define NGRP 4       // seg-groups; each sgemm block reduces 4 segs
#define SLOT 256     // max actives per 1024-i segment per (t,b)

// ---------------- scratch (static device memory; no runtime alloc) ----------------
__device__ unsigned g_masks[T_ * I_];                    // bit b = spike(b,i,t)
__device__ int      g_list2[B_ * T_ * NSEG * SLOT];      // slotted active-i lists
__device__ int      g_segLen[B_ * T_ * NSEG];
__device__ float    g_weff[(size_t)I_ * H_];             // weight * synaptic_strength
__device__ float    g_partial[(size_t)NGRP * 4 * T_ * H_ * 8]; // [grp*4+bg][t][h][bi]  (5.2 MB)
__device__ float    g_acc[32];                           // diag: v[0..9], rate[10..19], thr[20..29]
__device__ int      g_cnt;                               // last-block ticket for k_scan

// ---------------- kernel 0: fused spike-pack + w_eff materialization ----------------
// blocks [0,16): pack (1024 i's each); blocks [16,4112): weff (4096 elems each)
__global__ void __launch_bounds__(1024) k0(const float* __restrict__ spikes,
                                           const float* __restrict__ w,
                                           const float* __restrict__ s) {
    if (blockIdx.x < 16) {
        int i = blockIdx.x * 1024 + threadIdx.x;
        unsigned m[T_];
#pragma unroll
        for (int t = 0; t < T_; t++) m[t] = 0;
        const char* base = (const char*)spikes + (size_t)i * (T_ * 4);
#pragma unroll 4
        for (int b = 0; b < B_; b++) {
            const float2* p = (const float2*)(base + (size_t)b * ((size_t)I_ * T_ * 4));
            float2 v0 = p[0], v1 = p[1], v2 = p[2], v3 = p[3], v4 = p[4];
            unsigned bit = 1u << b;
            if (v0.x != 0.0f) m[0] |= bit;
            if (v0.y != 0.0f) m[1] |= bit;
            if (v1.x != 0.0f) m[2] |= bit;
            if (v1.y != 0.0f) m[3] |= bit;
            if (v2.x != 0.0f) m[4] |= bit;
            if (v2.y != 0.0f) m[5] |= bit;
            if (v3.x != 0.0f) m[6] |= bit;
            if (v3.y != 0.0f) m[7] |= bit;
            if (v4.x != 0.0f) m[8] |= bit;
            if (v4.y != 0.0f) m[9] |= bit;
        }
#pragma unroll
        for (int t = 0; t < T_; t++) g_masks[t * I_ + i] = m[t];
        if (blockIdx.x == 0 && threadIdx.x < 32) g_acc[threadIdx.x] = 0.0f;
        if (blockIdx.x == 0 && threadIdx.x == 0) g_cnt = 0;
    } else {
        size_t idx = ((size_t)(blockIdx.x - 16) * 1024 + threadIdx.x) * 4;
        float4 a = *(const float4*)(w + idx);
        float4 c = *(const float4*)(s + idx);
        float4 r;
        r.x = a.x * c.x; r.y = a.y * c.y; r.z = a.z * c.z; r.w = a.w * c.w;
        *(float4*)(&g_weff[idx]) = r;
    }
}

// ---------------- kernel 1: slotted compaction (deterministic, coalesced) ----------
__global__ void __launch_bounds__(256) k_lists() {
    int tb = blockIdx.x;         // t*32 + b
    int t  = tb >> 5;
    int b  = tb & 31;
    int tid = threadIdx.x;
    int seg = tid >> 4;
    int sub = tid & 15;
    const uint4* mrow4 = (const uint4*)(g_masks + t * I_ + seg * 1024);
    // pass 1: count
    int c = 0;
#pragma unroll
    for (int j = 0; j < 16; j++) {
        uint4 m4 = mrow4[sub + j * 16];
        c += ((m4.x >> b) & 1u) + ((m4.y >> b) & 1u) + ((m4.z >> b) & 1u) + ((m4.w >> b) & 1u);
    }
    // inclusive scan within 16-thread group
    int inc = c;
#pragma unroll
    for (int d = 1; d < 16; d <<= 1) {
        int n = __shfl_up_sync(0xffffffffu, inc, d, 16);
        if (sub >= d) inc += n;
    }
    int total = __shfl_sync(0xffffffffu, inc, 15, 16);
    int off = inc - c;
    if (sub == 0) g_segLen[tb * NSEG + seg] = total < SLOT ? total : SLOT;
    int* slot = g_list2 + ((size_t)tb * NSEG + seg) * SLOT;
    // pass 2: write (L1 hits)
#pragma unroll
    for (int j = 0; j < 16; j++) {
        uint4 m4 = mrow4[sub + j * 16];
        int i0 = seg * 1024 + sub * 4 + j * 64;
        if ((m4.x >> b) & 1u) { if (off < SLOT) slot[off] = i0 + 0; off++; }
        if ((m4.y >> b) & 1u) { if (off < SLOT) slot[off] = i0 + 1; off++; }
        if ((m4.z >> b) & 1u) { if (off < SLOT) slot[off] = i0 + 2; off++; }
        if ((m4.w >> b) & 1u) { if (off < SLOT) slot[off] = i0 + 3; off++; }
    }
}

// ---------------- kernel 2: sparse row-accumulate "GEMM", 4 segs per block ----------
// grid (NGRP, 8, T_*4): (seg-group, h-tile-128, t & batch-group); block 256: warp = b
// Per seg: temp-accumulate with the 4-unroll chain, then total += seg_sum (seg order kept).
__global__ void __launch_bounds__(256) k_sgemm() {
    int grp  = blockIdx.x;            // 0..3 -> segs [grp*4, grp*4+4)
    int hblk = blockIdx.y;
    int t    = blockIdx.z >> 2;
    int bg   = blockIdx.z & 3;
    int warp = threadIdx.x >> 5;
    int lane = threadIdx.x & 31;
    int b    = bg * 8 + warp;
    int tb   = t * 32 + b;
    const float* W = g_weff + hblk * 128 + lane * 4;
    float tx = 0.f, ty = 0.f, tz = 0.f, tw = 0.f;
#pragma unroll
    for (int sg = 0; sg < 4; sg++) {
        int seg = grp * 4 + sg;
        int len = g_segLen[tb * NSEG + seg];
        const int4* lst4 = (const int4*)(g_list2 + ((size_t)tb * NSEG + seg) * SLOT);
        float ax = 0.f, ay = 0.f, az = 0.f, aw = 0.f;
        int k4 = len >> 2;
        for (int q = 0; q < k4; q++) {
            int4 id = lst4[q];
            float4 w0 = *(const float4*)(W + (size_t)id.x * H_);
            float4 w1 = *(const float4*)(W + (size_t)id.y * H_);
            float4 w2 = *(const float4*)(W + (size_t)id.z * H_);
            float4 w3 = *(const float4*)(W + (size_t)id.w * H_);
            ax += w0.x; ay += w0.y; az += w0.z; aw += w0.w;
            ax += w1.x; ay += w1.y; az += w1.z; aw += w1.w;
            ax += w2.x; ay += w2.y; az += w2.z; aw += w2.w;
            ax += w3.x; ay += w3.y; az += w3.z; aw += w3.w;
        }
        for (int k = k4 * 4; k < len; k++) {
            int i = ((const int*)lst4)[k];
            float4 w0 = *(const float4*)(W + (size_t)i * H_);
            ax += w0.x; ay += w0.y; az += w0.z; aw += w0.w;
        }
        tx += ax; ty += ay; tz += az; tw += aw;
    }
    // transpose to [h][bi] via smem for coalesced reads downstream
    __shared__ float sh[8][132];
    sh[warp][lane * 4 + 0] = tx;
    sh[warp][lane * 4 + 1] = ty;
    sh[warp][lane * 4 + 2] = tz;
    sh[warp][lane * 4 + 3] = tw;
    __syncthreads();
    int h  = threadIdx.x >> 1;        // local h 0..127
    int hq = (threadIdx.x & 1) * 4;   // bi quad 0 or 4
    float4 o;
    o.x = sh[hq + 0][h]; o.y = sh[hq + 1][h]; o.z = sh[hq + 2][h]; o.w = sh[hq + 3][h];
    size_t sb = (size_t)grp * 4 + bg;
    float* dst = g_partial + ((sb * T_ + t) * H_ + (size_t)hblk * 128) * 8;
    *(float4*)(dst + h * 8 + hq) = o;
}

// ---------------- kernel 3: two-phase scan (R11 shape; phase 1 now only 4 slabs) ---
__global__ void __launch_bounds__(256) k_scan(const float* __restrict__ thr_in,
                                              const float* __restrict__ fre_in,
                                              const float* __restrict__ tau_mem,
                                              const float* __restrict__ tau_syn,
                                              const float* __restrict__ target,
                                              const float* __restrict__ lr,
                                              float* __restrict__ out) {
    __shared__ float sw[T_][8][32];   // [t][h_local][b]
    __shared__ float sacc[32];
    __shared__ int slast;
    if (threadIdx.x < 32) sacc[threadIdx.x] = 0.0f;

    int lane = threadIdx.x & 31;      // = b
    int hl   = threadIdx.x >> 5;      // h_local 0..7
    int hg   = blockIdx.x * 8 + hl;   // global h
    int bg   = lane >> 3;
    int bi   = lane & 7;

    // ---- phase 1: chain 4 grp slabs per (t, h, b); grp order 0..3
    const float* P = g_partial + ((size_t)bg * T_ * H_ + (size_t)hg) * 8 + bi;
#pragma unroll
    for (int t = 0; t < T_; t++) {
        float a = 0.0f;
#pragma unroll
        for (int grp = 0; grp < NGRP; grp++)
            a += P[((size_t)grp * 4 * T_ + t) * H_ * 8];
        sw[t][hl][lane] = a;
    }
    __syncthreads();

    // ---- phase 2: sequential scan
    float am  = expf(-0.001f / tau_mem[0]);
    float as  = expf(-0.001f / tau_syn[0]);
    float tgt = target[0];
    float hlr = lr[0];
    float thr = thr_in[hg];
    float fre = fre_in[hg];
    float v = 0.0f, isyn = 0.0f;
    float sp[T_];
#pragma unroll
    for (int t = 0; t < T_; t++) {
        float w = sw[t][hl][lane];
        isyn = as * isyn + w;
        v    = am * v + isyn;
        unsigned m = __ballot_sync(0xffffffffu, v >= thr);
        bool fired = (m >> lane) & 1u;
        if (fired) v -= thr;
        sp[t] = fired ? 1.0f : 0.0f;
        float rate = (float)__popc(m) * (1.0f / 32.0f);
        fre = 0.99f * fre + 0.01f * rate;
        thr += hlr * (fre - tgt);
        float vs = v;
#pragma unroll
        for (int o = 16; o > 0; o >>= 1) vs += __shfl_down_sync(0xffffffffu, vs, o);
        if (lane == 0) {
            atomicAdd(&sacc[t], vs);
            atomicAdd(&sacc[10 + t], rate);
            atomicAdd(&sacc[20 + t], thr);
        }
    }
    // spikes: out[b][h][t] — 40 contiguous bytes per thread, 5x float2
    float2* o2 = (float2*)(out + (size_t)lane * H_ * T_ + (size_t)hg * T_);
#pragma unroll
    for (int j = 0; j < 5; j++) {
        float2 p; p.x = sp[2 * j]; p.y = sp[2 * j + 1];
        o2[j] = p;
    }
    __syncthreads();
    if (threadIdx.x == 0) {
#pragma unroll
        for (int i = 0; i < 30; i++) atomicAdd(&g_acc[i], sacc[i]);
        __threadfence();
        int p = atomicAdd(&g_cnt, 1);
        slast = (p == (int)gridDim.x - 1);
    }
    __syncthreads();
    if (slast && threadIdx.x < 30) {
        float vfin = atomicAdd(&g_acc[threadIdx.x], 0.0f);  // coherent L2 read
        float scale = (threadIdx.x < 10) ? (1.0f / (B_ * H_)) : (1.0f / H_);
        out[(size_t)B_ * H_ * T_ + threadIdx.x] = vfin * scale;
    }
}

extern "C" void kernel_launch(void* const* d_in, const int* in_sizes, int n_in,
                              void* d_out, int out_size) {
    const float* spikes  = (const float*)d_in[0];
    const float* weight  = (const float*)d_in[1];
    const float* syn     = (const float*)d_in[2];
    const float* thr     = (const float*)d_in[3];
    const float* fre     = (const float*)d_in[4];
    const float* tau_mem = (const float*)d_in[5];
    const float* tau_syn = (const float*)d_in[6];
    const float* target  = (const float*)d_in[7];
    const float* lr      = (const float*)d_in[8];
    float* out = (float*)d_out;

    k0<<<16 + (int)((size_t)I_ * H_ / 4 / 1024), 1024>>>(spikes, weight, syn);
    k_lists<<<B_ * T_, 256>>>();
    k_sgemm<<<dim3(NGRP, 8, T_ * 4), 256>>>();
    k_scan<<<H_ / 8, 256>>>(thr, fre, tau_mem, tau_syn, target, lr, out);
}